// round 1
// baseline (speedup 1.0000x reference)
#include <cuda_runtime.h>
#include <math.h>

#define BATCH 512
#define SEQ   196
#define HID   1024
#define MID   512
#define FOUT  2048
#define NB    100
#define ROWS  (BATCH*SEQ)   // 100352

// Scratch (device globals: no allocation allowed)
__device__ __align__(16) float g_att[ROWS];
__device__ __align__(16) float g_ctx[BATCH*HID];

// ---------------------------------------------------------------------------
// Kernel 0: init att logits to b2
// ---------------------------------------------------------------------------
__global__ void k_init_att(const float* __restrict__ b2) {
    int i = blockIdx.x * blockDim.x + threadIdx.x;
    if (i < ROWS) g_att[i] = b2[0];
}

__device__ __forceinline__ unsigned f2tf32(float x) {
    unsigned y;
    asm("cvt.rna.tf32.f32 %0, %1;" : "=r"(y) : "f"(x));
    return y;
}

// ---------------------------------------------------------------------------
// Kernel 1: att[r] += sum_m relu(x[r]·W1[m] + b1[m]) * W2[m]
// Tiled GEMM: BM=128 rows, BN=128 of the 512 MLP cols, K=1024, tf32 mma.sync.
// Each CTA reduces its 128-col slice after relu and atomically adds per-row.
// ---------------------------------------------------------------------------
#define BM 128
#define BN 128
#define BK 16
#define XS 20   // padded smem row stride (words); 20 mod 32 -> conflict-free frag loads

__global__ __launch_bounds__(256, 2)
void k_gemm_att(const float* __restrict__ x,
                const float* __restrict__ W1,
                const float* __restrict__ b1,
                const float* __restrict__ W2) {
    __shared__ unsigned smx[2][BM][XS];
    __shared__ unsigned smw[2][BN][XS];
    __shared__ float s_b1[BN], s_w2[BN];
    __shared__ float s_part[BM];

    const int tid = threadIdx.x;
    const int rowBase = blockIdx.x * BM;
    const int colBase = blockIdx.y * BN;

    if (tid < BN) { s_b1[tid] = b1[colBase + tid]; s_w2[tid] = W2[colBase + tid]; }
    if (tid < BM) s_part[tid] = 0.f;

    const int lr = tid >> 2;          // 0..63
    const int lc = (tid & 3) * 4;     // 0,4,8,12

    const int warp = tid >> 5, lane = tid & 31;
    const int wm = warp & 3, wn = warp >> 2;   // 4 m-warps x 2 n-warps
    const int mBase = wm * 32, nBase = wn * 64;
    const int g = lane >> 2, t = lane & 3;

    float acc[2][8][4];
    #pragma unroll
    for (int mi = 0; mi < 2; mi++)
        #pragma unroll
        for (int ni = 0; ni < 8; ni++)
            #pragma unroll
            for (int q = 0; q < 4; q++) acc[mi][ni][q] = 0.f;

    float4 px[2], pw[2];

    // stage 0 load
    {
        #pragma unroll
        for (int i = 0; i < 2; i++) {
            int r = lr + i * 64;
            px[i] = *(const float4*)&x [(size_t)(rowBase + r) * HID + lc];
            pw[i] = *(const float4*)&W1[(size_t)(colBase + r) * HID + lc];
        }
        #pragma unroll
        for (int i = 0; i < 2; i++) {
            int r = lr + i * 64;
            smx[0][r][lc+0] = f2tf32(px[i].x); smx[0][r][lc+1] = f2tf32(px[i].y);
            smx[0][r][lc+2] = f2tf32(px[i].z); smx[0][r][lc+3] = f2tf32(px[i].w);
            smw[0][r][lc+0] = f2tf32(pw[i].x); smw[0][r][lc+1] = f2tf32(pw[i].y);
            smw[0][r][lc+2] = f2tf32(pw[i].z); smw[0][r][lc+3] = f2tf32(pw[i].w);
        }
    }
    __syncthreads();

    const int NT = HID / BK;  // 64
    for (int kt = 0; kt < NT; ++kt) {
        const int buf = kt & 1;
        if (kt < NT - 1) {
            int k0 = (kt + 1) * BK;
            #pragma unroll
            for (int i = 0; i < 2; i++) {
                int r = lr + i * 64;
                px[i] = *(const float4*)&x [(size_t)(rowBase + r) * HID + k0 + lc];
                pw[i] = *(const float4*)&W1[(size_t)(colBase + r) * HID + k0 + lc];
            }
        }
        #pragma unroll
        for (int ks = 0; ks < 2; ++ks) {
            const int k0s = ks * 8;
            unsigned a[2][4], bf[8][2];
            #pragma unroll
            for (int mi = 0; mi < 2; mi++) {
                int r0 = mBase + mi * 16 + g;
                a[mi][0] = smx[buf][r0    ][k0s + t];
                a[mi][1] = smx[buf][r0 + 8][k0s + t];
                a[mi][2] = smx[buf][r0    ][k0s + t + 4];
                a[mi][3] = smx[buf][r0 + 8][k0s + t + 4];
            }
            #pragma unroll
            for (int ni = 0; ni < 8; ni++) {
                int c0 = nBase + ni * 8 + g;
                bf[ni][0] = smw[buf][c0][k0s + t];
                bf[ni][1] = smw[buf][c0][k0s + t + 4];
            }
            #pragma unroll
            for (int mi = 0; mi < 2; mi++)
                #pragma unroll
                for (int ni = 0; ni < 8; ni++) {
                    asm volatile(
                        "mma.sync.aligned.m16n8k8.row.col.f32.tf32.tf32.f32 "
                        "{%0,%1,%2,%3},{%4,%5,%6,%7},{%8,%9},{%0,%1,%2,%3};"
                        : "+f"(acc[mi][ni][0]), "+f"(acc[mi][ni][1]),
                          "+f"(acc[mi][ni][2]), "+f"(acc[mi][ni][3])
                        : "r"(a[mi][0]), "r"(a[mi][1]), "r"(a[mi][2]), "r"(a[mi][3]),
                          "r"(bf[ni][0]), "r"(bf[ni][1]));
                }
        }
        if (kt < NT - 1) {
            int nb = buf ^ 1;
            #pragma unroll
            for (int i = 0; i < 2; i++) {
                int r = lr + i * 64;
                smx[nb][r][lc+0] = f2tf32(px[i].x); smx[nb][r][lc+1] = f2tf32(px[i].y);
                smx[nb][r][lc+2] = f2tf32(px[i].z); smx[nb][r][lc+3] = f2tf32(px[i].w);
                smw[nb][r][lc+0] = f2tf32(pw[i].x); smw[nb][r][lc+1] = f2tf32(pw[i].y);
                smw[nb][r][lc+2] = f2tf32(pw[i].z); smw[nb][r][lc+3] = f2tf32(pw[i].w);
            }
        }
        __syncthreads();
    }

    // Epilogue: relu(acc + b1) * W2, reduce over the 128 cols of this CTA.
    float rs00 = 0.f, rs01 = 0.f, rs10 = 0.f, rs11 = 0.f;
    #pragma unroll
    for (int mi = 0; mi < 2; mi++) {
        float s0 = 0.f, s1 = 0.f;
        #pragma unroll
        for (int ni = 0; ni < 8; ni++) {
            int c = nBase + ni * 8 + t * 2;
            float v0 = fmaxf(acc[mi][ni][0] + s_b1[c],     0.f) * s_w2[c];
            float v1 = fmaxf(acc[mi][ni][1] + s_b1[c + 1], 0.f) * s_w2[c + 1];
            float v2 = fmaxf(acc[mi][ni][2] + s_b1[c],     0.f) * s_w2[c];
            float v3 = fmaxf(acc[mi][ni][3] + s_b1[c + 1], 0.f) * s_w2[c + 1];
            s0 += v0 + v1;
            s1 += v2 + v3;
        }
        if (mi == 0) { rs00 = s0; rs01 = s1; } else { rs10 = s0; rs11 = s1; }
    }
    #pragma unroll
    for (int off = 1; off < 4; off <<= 1) {
        rs00 += __shfl_xor_sync(0xffffffff, rs00, off);
        rs01 += __shfl_xor_sync(0xffffffff, rs01, off);
        rs10 += __shfl_xor_sync(0xffffffff, rs10, off);
        rs11 += __shfl_xor_sync(0xffffffff, rs11, off);
    }
    if (t == 0) {
        atomicAdd(&s_part[mBase + g],      rs00);
        atomicAdd(&s_part[mBase + 8 + g],  rs01);
        atomicAdd(&s_part[mBase + 16 + g], rs10);
        atomicAdd(&s_part[mBase + 24 + g], rs11);
    }
    __syncthreads();
    if (tid < BM) atomicAdd(&g_att[rowBase + tid], s_part[tid]);
}

// ---------------------------------------------------------------------------
// Kernel 2: per-batch softmax -> moments -> 2x2 algebra -> r -> w -> context
// One CTA per batch; streams x[b] once (memory-bound phase).
// ---------------------------------------------------------------------------
__global__ __launch_bounds__(256)
void k_stats_ctx(const float* __restrict__ x,
                 const unsigned char* __restrict__ mask,
                 const float* __restrict__ G,
                 const float* __restrict__ mub) {
    __shared__ float sbuf[256];
    __shared__ float r_s[NB];
    __shared__ float w_s[SEQ];

    const int b = blockIdx.x, tid = threadIdx.x;

    float logit = -3.0e38f;
    if (tid < SEQ) {
        logit = g_att[b * SEQ + tid];
        if (mask[b * SEQ + tid]) logit = -1.0e9f;
    }
    // max
    sbuf[tid] = logit; __syncthreads();
    for (int s = 128; s > 0; s >>= 1) {
        if (tid < s) sbuf[tid] = fmaxf(sbuf[tid], sbuf[tid + s]);
        __syncthreads();
    }
    float mx = sbuf[0]; __syncthreads();

    float e = (tid < SEQ) ? expf(logit - mx) : 0.f;
    float px = 0.f, py = 0.f;
    if (tid < SEQ) {
        px = (float)(tid / 14) * (1.f / 13.f);
        py = (float)(tid % 14) * (1.f / 13.f);
    }
    float vals[6] = { e, e * px, e * py, e * px * px, e * px * py, e * py * py };
    float sums[6];
    #pragma unroll
    for (int q = 0; q < 6; q++) {
        sbuf[tid] = vals[q]; __syncthreads();
        for (int s = 128; s > 0; s >>= 1) {
            if (tid < s) sbuf[tid] += sbuf[tid + s];
            __syncthreads();
        }
        sums[q] = sbuf[0]; __syncthreads();
    }

    // Identical scalar chain in every thread (bitwise-same results, no broadcast needed)
    const float S   = sums[0];
    const float Mux = sums[1] / S, Muy = sums[2] / S;
    float S00 = sums[3] / S - Mux * Mux + 1e-6f;
    float S01 = sums[4] / S - Mux * Muy;
    float S11 = sums[5] / S - Muy * Muy + 1e-6f;

    float det = S00 * S11 - S01 * S01;
    float I00 = S11 / det, I01 = -S01 / det, I11 = S00 / det;     // Sinv == Ssym
    float t0 = I00 * Mux + I01 * Muy;
    float t1 = I01 * Mux + I11 * Muy;
    float ds = I00 * I11 - I01 * I01;
    float R00 = I11 / ds, R01 = -I01 / ds, R11 = I00 / ds;        // Sigma_r
    float m0 = R00 * t0 + R01 * t1;
    float m1 = R01 * t0 + R11 * t1;                               // mu_r
    float A00 = R00 + 1e-3f, A01 = R01, A11 = R11 + 1e-3f;
    float detA = A00 * A11 - A01 * A01;
    float Ai00 = A11 / detA, Ai01 = -A01 / detA, Ai11 = A00 / detA;
    float coef = 1.f / (6.2831853071795864769f * sqrtf(detA));

    if (tid < NB) {
        float d0 = m0 - mub[2 * tid];
        float d1 = m1 - mub[2 * tid + 1];
        float quad = d0 * (Ai00 * d0 + Ai01 * d1) + d1 * (Ai01 * d0 + Ai11 * d1);
        r_s[tid] = expf(-0.5f * quad) * coef;
    }
    __syncthreads();

    if (tid < SEQ) {
        float wv = 0.f;
        #pragma unroll 4
        for (int k = 0; k < NB; k++) wv += G[tid * NB + k] * r_s[k];
        w_s[tid] = wv;
    }
    __syncthreads();

    // context[b, tid*4 .. +3] = sum_n w[n] * x[b,n,:]
    const float4* xb = (const float4*)(x + (size_t)b * SEQ * HID);
    float ax = 0.f, ay = 0.f, az = 0.f, aw = 0.f;
    #pragma unroll 4
    for (int n = 0; n < SEQ; n++) {
        float4 v = xb[n * (HID / 4) + tid];
        float wv = w_s[n];
        ax += wv * v.x; ay += wv * v.y; az += wv * v.z; aw += wv * v.w;
    }
    float4 o; o.x = ax; o.y = ay; o.z = az; o.w = aw;
    ((float4*)(g_ctx + (size_t)b * HID))[tid] = o;
}

// ---------------------------------------------------------------------------
// Kernel 3: out = ctx(512x1024) @ Wm^T(1024x2048) + bm   (fp32, 64x64 tiles)
// ---------------------------------------------------------------------------
#define BM4 64
#define BN4 64
#define BK4 16
#define ST4 68

__global__ __launch_bounds__(256)
void k_out(const float* __restrict__ Wm, const float* __restrict__ bm,
           float* __restrict__ out) {
    __shared__ float sa[BK4][ST4];
    __shared__ float sb[BK4][ST4];

    const int tid = threadIdx.x;
    const int mB = blockIdx.x * BM4, nB = blockIdx.y * BN4;
    const int lr = tid >> 2, lc = tid & 3;
    const int tm = tid >> 4, tn = tid & 15;

    float acc[4][4];
    #pragma unroll
    for (int i = 0; i < 4; i++)
        #pragma unroll
        for (int j = 0; j < 4; j++) acc[i][j] = 0.f;

    for (int k0 = 0; k0 < HID; k0 += BK4) {
        float4 va = *(const float4*)&g_ctx[(size_t)(mB + lr) * HID + k0 + lc * 4];
        float4 vb = *(const float4*)&Wm  [(size_t)(nB + lr) * HID + k0 + lc * 4];
        __syncthreads();
        sa[lc*4+0][lr] = va.x; sa[lc*4+1][lr] = va.y; sa[lc*4+2][lr] = va.z; sa[lc*4+3][lr] = va.w;
        sb[lc*4+0][lr] = vb.x; sb[lc*4+1][lr] = vb.y; sb[lc*4+2][lr] = vb.z; sb[lc*4+3][lr] = vb.w;
        __syncthreads();
        #pragma unroll
        for (int k = 0; k < BK4; k++) {
            float4 a4 = *(const float4*)&sa[k][tm * 4];
            float4 b4 = *(const float4*)&sb[k][tn * 4];
            acc[0][0] += a4.x * b4.x; acc[0][1] += a4.x * b4.y; acc[0][2] += a4.x * b4.z; acc[0][3] += a4.x * b4.w;
            acc[1][0] += a4.y * b4.x; acc[1][1] += a4.y * b4.y; acc[1][2] += a4.y * b4.z; acc[1][3] += a4.y * b4.w;
            acc[2][0] += a4.z * b4.x; acc[2][1] += a4.z * b4.y; acc[2][2] += a4.z * b4.z; acc[2][3] += a4.z * b4.w;
            acc[3][0] += a4.w * b4.x; acc[3][1] += a4.w * b4.y; acc[3][2] += a4.w * b4.z; acc[3][3] += a4.w * b4.w;
        }
    }
    #pragma unroll
    for (int i = 0; i < 4; i++) {
        int r = mB + tm * 4 + i;
        #pragma unroll
        for (int j = 0; j < 4; j++) {
            int c = nB + tn * 4 + j;
            out[(size_t)r * FOUT + c] = acc[i][j] + bm[c];
        }
    }
}

// ---------------------------------------------------------------------------
extern "C" void kernel_launch(void* const* d_in, const int* in_sizes, int n_in,
                              void* d_out, int out_size) {
    const float*         x   = (const float*)d_in[0];
    const unsigned char* xm  = (const unsigned char*)d_in[1];
    const float*         W1  = (const float*)d_in[2];
    const float*         b1  = (const float*)d_in[3];
    const float*         W2  = (const float*)d_in[4];
    const float*         b2  = (const float*)d_in[5];
    const float*         Wm  = (const float*)d_in[6];
    const float*         bm  = (const float*)d_in[7];
    const float*         G   = (const float*)d_in[8];
    const float*         mub = (const float*)d_in[9];
    float* out = (float*)d_out;

    k_init_att<<<ROWS / 1024, 1024>>>(b2);                       // 98 blocks, exact
    k_gemm_att<<<dim3(ROWS / BM, MID / BN), 256>>>(x, W1, b1, W2);
    k_stats_ctx<<<BATCH, 256>>>(x, xm, G, mub);
    k_out<<<dim3(BATCH / BM4, FOUT / BN4), 256>>>(Wm, bm, out);
}

// round 3
// speedup vs baseline: 1.8494x; 1.8494x over previous
#include <cuda_runtime.h>
#include <cuda_bf16.h>
#include <math.h>
#include <stdint.h>

#define BATCH 512
#define SEQ   196
#define HID   1024
#define MID   512
#define FOUT  2048
#define NB    100
#define ROWS  (BATCH*SEQ)   // 100352

// Scratch (device globals: no allocation allowed)
__device__ __align__(16) float g_att[ROWS];
__device__ __align__(16) float g_ctx[BATCH*HID];
__device__ __align__(16) __nv_bfloat16 g_w1b[MID*HID];   // W1 pre-converted to bf16

// ===========================================================================
// Helpers
// ===========================================================================
__device__ __forceinline__ unsigned pack_bf16(float lo, float hi) {
    unsigned r;
    asm("cvt.rn.bf16x2.f32 %0, %1, %2;" : "=r"(r) : "f"(hi), "f"(lo));
    return r;
}
__device__ __forceinline__ unsigned f2tf32(float x) {
    unsigned y;
    asm("cvt.rna.tf32.f32 %0, %1;" : "=r"(y) : "f"(x));
    return y;
}
__device__ __forceinline__ uint32_t smem_u32(const void* p) {
    uint32_t a;
    asm("{ .reg .u64 t; cvta.to.shared.u64 t, %1; cvt.u32.u64 %0, t; }" : "=r"(a) : "l"(p));
    return a;
}

// 64B-row swizzle (SW64): XOR bits [5:4] with bits [8:7]
#define SWZ64(o) ((o) ^ (((o) >> 3) & 0x30))

#define STS128U(addr, r0, r1, r2, r3) \
    asm volatile("st.shared.v4.b32 [%0], {%1,%2,%3,%4};" \
                 :: "r"(addr), "r"(r0), "r"(r1), "r"(r2), "r"(r3) : "memory")

#define LDSM_X4(r0, r1, r2, r3, addr) \
    asm volatile("ldmatrix.sync.aligned.m8n8.x4.shared.b16 {%0,%1,%2,%3}, [%4];" \
                 : "=r"(r0), "=r"(r1), "=r"(r2), "=r"(r3) : "r"(addr))

#define MMA_BF16(d, a0, a1, a2, a3, b0, b1) \
    asm volatile("mma.sync.aligned.m16n8k16.row.col.f32.bf16.bf16.f32 " \
                 "{%0,%1,%2,%3},{%4,%5,%6,%7},{%8,%9},{%0,%1,%2,%3};" \
                 : "+f"((d)[0]), "+f"((d)[1]), "+f"((d)[2]), "+f"((d)[3]) \
                 : "r"(a0), "r"(a1), "r"(a2), "r"(a3), "r"(b0), "r"(b1))

// ===========================================================================
// Kernel 0: zero att accumulator
// ===========================================================================
__global__ void k_init_att() {
    int i = blockIdx.x * blockDim.x + threadIdx.x;
    if (i < ROWS) g_att[i] = 0.f;
}

// ===========================================================================
// Kernel A: convert W1 (fp32) -> g_w1b (bf16)
// ===========================================================================
__global__ void k_cvt_w1(const float* __restrict__ W1) {
    int i = blockIdx.x * blockDim.x + threadIdx.x;     // 0..131071 (x4 elems)
    float4 v = ((const float4*)W1)[i];
    unsigned u0 = pack_bf16(v.x, v.y);
    unsigned u1 = pack_bf16(v.z, v.w);
    ((uint2*)g_w1b)[i] = make_uint2(u0, u1);
}

// ===========================================================================
// Kernel B: bf16 mma.sync GEMM + fused relu/W2 row-sum epilogue -> g_att
//   BM=128 rows, BN=128 mid-cols, BK=32, double-buffered SW64 smem, ldmatrix.
//   grid (4 n-tiles fastest, 784 row-tiles) for L2 reuse of x.
// ===========================================================================
#define BKG 32          // K per stage (bf16 elems) = 64 bytes/row
#define NKT (HID/BKG)   // 32 iterations

__global__ __launch_bounds__(256, 2)
void k_mlp_att(const float* __restrict__ x,
               const float* __restrict__ b1,
               const float* __restrict__ W2) {
    // 8KB per tile stage; 1024-aligned so SWZ64 (bits 7-8) is base-invariant
    __shared__ __align__(1024) char smA[2][128 * 64];
    __shared__ __align__(1024) char smB[2][128 * 64];
    __shared__ float b1s[128], w2s[128], s_part[128];

    const int tid  = threadIdx.x;
    const int lane = tid & 31;
    const int warp = tid >> 5;
    const int colBase = blockIdx.x * 128;     // n tile (fastest-varying)
    const int rowBase = blockIdx.y * 128;     // row tile

    const uint32_t sa0 = smem_u32(&smA[0][0]);
    const uint32_t sa1 = smem_u32(&smA[1][0]);
    const uint32_t sb0 = smem_u32(&smB[0][0]);
    const uint32_t sb1 = smem_u32(&smB[1][0]);

    if (tid < 128) {
        b1s[tid] = b1[colBase + tid];
        w2s[tid] = W2[colBase + tid];
        s_part[tid] = 0.f;
    }

    // warp tiling: 4 m-warps x 2 n-warps, warp tile 32m x 64n
    const int wm = warp & 3, wn = warp >> 2;
    const int mBase = wm * 32, nBase = wn * 64;
    const int g = lane >> 2, t = lane & 3;

    // ldmatrix lane-address components (offsets within a stage)
    // A: row = mBase + mi*16 + (lane&15), kb = ks*32 + (lane>>4)*16
    const int aRow = mBase + (lane & 15);
    const int aKb  = (lane >> 4) * 16;
    // B: row = nBase + nj*16 + (lane&7) + (lane>>4)*8, kb = ks*32 + ((lane>>3)&1)*16
    const int bRow = nBase + (lane & 7) + ((lane >> 4) * 8);
    const int bKb  = ((lane >> 3) & 1) * 16;

    uint32_t aOff[2][2], bOff[4][2];   // [mi][ks], [nj][ks]  (swizzled, stage-relative)
    #pragma unroll
    for (int mi = 0; mi < 2; mi++)
        #pragma unroll
        for (int ks = 0; ks < 2; ks++)
            aOff[mi][ks] = SWZ64((uint32_t)((aRow + mi * 16) * 64 + ks * 32 + aKb));
    #pragma unroll
    for (int nj = 0; nj < 4; nj++)
        #pragma unroll
        for (int ks = 0; ks < 2; ks++)
            bOff[nj][ks] = SWZ64((uint32_t)((bRow + nj * 16) * 64 + ks * 32 + bKb));

    float acc[2][8][4];
    #pragma unroll
    for (int mi = 0; mi < 2; mi++)
        #pragma unroll
        for (int ni = 0; ni < 8; ni++)
            #pragma unroll
            for (int q = 0; q < 4; q++) acc[mi][ni][q] = 0.f;

    // ---- stage loaders ----
    // A: 128 rows x 32 fp32 -> bf16. 512 tasks of 8 floats, 2 iters.
    const int arow0 = tid >> 2;            // task row for it=0 (task=tid)
    const int ac8   = (tid & 3) * 8;       // float col within k-chunk
    // B: 128 rows x 32 bf16 = 64B rows, 512 tasks of 16B.
    auto ldA = [&](int kc, float4* st) {
        const int k0 = kc * BKG;
        #pragma unroll
        for (int it = 0; it < 2; ++it) {
            int row = arow0 + it * 64;
            const float4* p = (const float4*)(x + (size_t)(rowBase + row) * HID + k0 + ac8);
            st[it * 2]     = p[0];
            st[it * 2 + 1] = p[1];
        }
    };
    auto stA = [&](uint32_t base, const float4* st) {
        #pragma unroll
        for (int it = 0; it < 2; ++it) {
            int row = arow0 + it * 64;
            float4 v0 = st[it * 2], v1 = st[it * 2 + 1];
            unsigned u0 = pack_bf16(v0.x, v0.y), u1 = pack_bf16(v0.z, v0.w);
            unsigned u2 = pack_bf16(v1.x, v1.y), u3 = pack_bf16(v1.z, v1.w);
            uint32_t off = (uint32_t)(row * 64 + ac8 * 2);
            STS128U(base + SWZ64(off), u0, u1, u2, u3);
        }
    };
    auto ldB = [&](int kc, uint4* st) {
        const int k0 = kc * BKG;
        #pragma unroll
        for (int it = 0; it < 2; ++it) {
            int task = tid + it * 256;
            int row = task >> 2;
            int e8  = (task & 3) * 8;   // bf16 element offset
            st[it] = *(const uint4*)(g_w1b + (size_t)(colBase + row) * HID + k0 + e8);
        }
    };
    auto stB = [&](uint32_t base, const uint4* st) {
        #pragma unroll
        for (int it = 0; it < 2; ++it) {
            int task = tid + it * 256;
            int row = task >> 2;
            int c16 = (task & 3) * 16;
            uint32_t off = (uint32_t)(row * 64 + c16);
            STS128U(base + SWZ64(off), st[it].x, st[it].y, st[it].z, st[it].w);
        }
    };

    // prologue: fill stage 0
    {
        float4 fa[4]; uint4 fb[2];
        ldA(0, fa); ldB(0, fb);
        stA(sa0, fa); stB(sb0, fb);
    }
    __syncthreads();

    float4 fa[4]; uint4 fb[2];
    for (int kt = 0; kt < NKT; ++kt) {
        const uint32_t aBase = (kt & 1) ? sa1 : sa0;
        const uint32_t bBase = (kt & 1) ? sb1 : sb0;
        if (kt < NKT - 1) { ldA(kt + 1, fa); ldB(kt + 1, fb); }

        #pragma unroll
        for (int ks = 0; ks < 2; ++ks) {
            uint32_t a[2][4];
            #pragma unroll
            for (int mi = 0; mi < 2; mi++)
                LDSM_X4(a[mi][0], a[mi][1], a[mi][2], a[mi][3], aBase + aOff[mi][ks]);
            #pragma unroll
            for (int nj = 0; nj < 4; nj++) {
                uint32_t b0, b1r, b2, b3;
                LDSM_X4(b0, b1r, b2, b3, bBase + bOff[nj][ks]);
                #pragma unroll
                for (int mi = 0; mi < 2; mi++) {
                    MMA_BF16(acc[mi][nj * 2],     a[mi][0], a[mi][1], a[mi][2], a[mi][3], b0, b1r);
                    MMA_BF16(acc[mi][nj * 2 + 1], a[mi][0], a[mi][1], a[mi][2], a[mi][3], b2, b3);
                }
            }
        }
        if (kt < NKT - 1) {
            const uint32_t aN = (kt & 1) ? sa0 : sa1;
            const uint32_t bN = (kt & 1) ? sb0 : sb1;
            stA(aN, fa); stB(bN, fb);
        }
        __syncthreads();
    }

    // Epilogue: relu(acc + b1) * W2, reduce over this CTA's 128 cols.
    float rs00 = 0.f, rs01 = 0.f, rs10 = 0.f, rs11 = 0.f;
    #pragma unroll
    for (int mi = 0; mi < 2; mi++) {
        float s0 = 0.f, s1 = 0.f;
        #pragma unroll
        for (int ni = 0; ni < 8; ni++) {
            int c = nBase + ni * 8 + t * 2;
            float v0 = fmaxf(acc[mi][ni][0] + b1s[c],     0.f) * w2s[c];
            float v1 = fmaxf(acc[mi][ni][1] + b1s[c + 1], 0.f) * w2s[c + 1];
            float v2 = fmaxf(acc[mi][ni][2] + b1s[c],     0.f) * w2s[c];
            float v3 = fmaxf(acc[mi][ni][3] + b1s[c + 1], 0.f) * w2s[c + 1];
            s0 += v0 + v1;
            s1 += v2 + v3;
        }
        if (mi == 0) { rs00 = s0; rs01 = s1; } else { rs10 = s0; rs11 = s1; }
    }
    #pragma unroll
    for (int off = 1; off < 4; off <<= 1) {
        rs00 += __shfl_xor_sync(0xffffffff, rs00, off);
        rs01 += __shfl_xor_sync(0xffffffff, rs01, off);
        rs10 += __shfl_xor_sync(0xffffffff, rs10, off);
        rs11 += __shfl_xor_sync(0xffffffff, rs11, off);
    }
    if (t == 0) {
        atomicAdd(&s_part[mBase + g],      rs00);
        atomicAdd(&s_part[mBase + 8 + g],  rs01);
        atomicAdd(&s_part[mBase + 16 + g], rs10);
        atomicAdd(&s_part[mBase + 24 + g], rs11);
    }
    __syncthreads();
    if (tid < 128) atomicAdd(&g_att[rowBase + tid], s_part[tid]);
}

// ===========================================================================
// Kernel C: per-batch softmax -> moments -> 2x2 algebra -> r -> w -> context
// ===========================================================================
__global__ __launch_bounds__(256)
void k_stats_ctx(const float* __restrict__ x,
                 const unsigned char* __restrict__ mask,
                 const float* __restrict__ G,
                 const float* __restrict__ mub) {
    __shared__ float sbuf[256];
    __shared__ float r_s[NB];
    __shared__ float w_s[SEQ];

    const int b = blockIdx.x, tid = threadIdx.x;

    float logit = -3.0e38f;
    if (tid < SEQ) {
        logit = g_att[b * SEQ + tid];
        if (mask[b * SEQ + tid]) logit = -1.0e9f;
    }
    sbuf[tid] = logit; __syncthreads();
    for (int s = 128; s > 0; s >>= 1) {
        if (tid < s) sbuf[tid] = fmaxf(sbuf[tid], sbuf[tid + s]);
        __syncthreads();
    }
    float mx = sbuf[0]; __syncthreads();

    float e = (tid < SEQ) ? expf(logit - mx) : 0.f;
    float px = 0.f, py = 0.f;
    if (tid < SEQ) {
        px = (float)(tid / 14) * (1.f / 13.f);
        py = (float)(tid % 14) * (1.f / 13.f);
    }
    float vals[6] = { e, e * px, e * py, e * px * px, e * px * py, e * py * py };
    float sums[6];
    #pragma unroll
    for (int q = 0; q < 6; q++) {
        sbuf[tid] = vals[q]; __syncthreads();
        for (int s = 128; s > 0; s >>= 1) {
            if (tid < s) sbuf[tid] += sbuf[tid + s];
            __syncthreads();
        }
        sums[q] = sbuf[0]; __syncthreads();
    }

    const float S   = sums[0];
    const float Mux = sums[1] / S, Muy = sums[2] / S;
    float S00 = sums[3] / S - Mux * Mux + 1e-6f;
    float S01 = sums[4] / S - Mux * Muy;
    float S11 = sums[5] / S - Muy * Muy + 1e-6f;

    float det = S00 * S11 - S01 * S01;
    float I00 = S11 / det, I01 = -S01 / det, I11 = S00 / det;
    float t0 = I00 * Mux + I01 * Muy;
    float t1 = I01 * Mux + I11 * Muy;
    float ds = I00 * I11 - I01 * I01;
    float R00 = I11 / ds, R01 = -I01 / ds, R11 = I00 / ds;
    float m0 = R00 * t0 + R01 * t1;
    float m1 = R01 * t0 + R11 * t1;
    float A00 = R00 + 1e-3f, A01 = R01, A11 = R11 + 1e-3f;
    float detA = A00 * A11 - A01 * A01;
    float Ai00 = A11 / detA, Ai01 = -A01 / detA, Ai11 = A00 / detA;
    float coef = 1.f / (6.2831853071795864769f * sqrtf(detA));

    if (tid < NB) {
        float d0 = m0 - mub[2 * tid];
        float d1 = m1 - mub[2 * tid + 1];
        float quad = d0 * (Ai00 * d0 + Ai01 * d1) + d1 * (Ai01 * d0 + Ai11 * d1);
        r_s[tid] = expf(-0.5f * quad) * coef;
    }
    __syncthreads();

    if (tid < SEQ) {
        float wv = 0.f;
        #pragma unroll 4
        for (int k = 0; k < NB; k++) wv += G[tid * NB + k] * r_s[k];
        w_s[tid] = wv;
    }
    __syncthreads();

    const float4* xb = (const float4*)(x + (size_t)b * SEQ * HID);
    float ax = 0.f, ay = 0.f, az = 0.f, aw = 0.f;
    #pragma unroll 4
    for (int n = 0; n < SEQ; n++) {
        float4 v = xb[n * (HID / 4) + tid];
        float wv = w_s[n];
        ax += wv * v.x; ay += wv * v.y; az += wv * v.z; aw += wv * v.w;
    }
    float4 o; o.x = ax; o.y = ay; o.z = az; o.w = aw;
    ((float4*)(g_ctx + (size_t)b * HID))[tid] = o;
}

// ===========================================================================
// Kernel D: out = ctx(512x1024) @ Wm^T(1024x2048) + bm   (tf32 mma.sync)
//   BM=64, BN=128, BK=16, 256 threads, grid (8,16) = 128 CTAs
// ===========================================================================
#define BM2 64
#define BN2 128
#define XS2 20

__global__ __launch_bounds__(256, 2)
void k_out2(const float* __restrict__ Wm, const float* __restrict__ bm,
            float* __restrict__ out) {
    __shared__ unsigned sa[2][BM2][XS2];
    __shared__ unsigned sbm[2][BN2][XS2];

    const int tid = threadIdx.x;
    const int mB = blockIdx.x * BM2;
    const int nB = blockIdx.y * BN2;

    const int lr = tid >> 2;          // 0..63
    const int lc = (tid & 3) * 4;     // 0,4,8,12

    const int warp = tid >> 5, lane = tid & 31;
    const int wm = warp & 1, wn = warp >> 1;   // 2 m-warps x 4 n-warps
    const int mBase = wm * 32, nBase = wn * 32;
    const int g = lane >> 2, t = lane & 3;

    float acc[2][4][4];
    #pragma unroll
    for (int mi = 0; mi < 2; mi++)
        #pragma unroll
        for (int ni = 0; ni < 4; ni++)
            #pragma unroll
            for (int q = 0; q < 4; q++) acc[mi][ni][q] = 0.f;

    float4 pa, pb0, pb1;
    {
        pa  = *(const float4*)&g_ctx[(size_t)(mB + lr) * HID + lc];
        pb0 = *(const float4*)&Wm  [(size_t)(nB + lr) * HID + lc];
        pb1 = *(const float4*)&Wm  [(size_t)(nB + lr + 64) * HID + lc];
        sa [0][lr][lc+0] = f2tf32(pa.x);  sa [0][lr][lc+1] = f2tf32(pa.y);
        sa [0][lr][lc+2] = f2tf32(pa.z);  sa [0][lr][lc+3] = f2tf32(pa.w);
        sbm[0][lr][lc+0] = f2tf32(pb0.x); sbm[0][lr][lc+1] = f2tf32(pb0.y);
        sbm[0][lr][lc+2] = f2tf32(pb0.z); sbm[0][lr][lc+3] = f2tf32(pb0.w);
        sbm[0][lr+64][lc+0] = f2tf32(pb1.x); sbm[0][lr+64][lc+1] = f2tf32(pb1.y);
        sbm[0][lr+64][lc+2] = f2tf32(pb1.z); sbm[0][lr+64][lc+3] = f2tf32(pb1.w);
    }
    __syncthreads();

    const int NT = HID / 16;  // 64
    for (int kt = 0; kt < NT; ++kt) {
        const int buf = kt & 1;
        if (kt < NT - 1) {
            int k0 = (kt + 1) * 16;
            pa  = *(const float4*)&g_ctx[(size_t)(mB + lr) * HID + k0 + lc];
            pb0 = *(const float4*)&Wm  [(size_t)(nB + lr) * HID + k0 + lc];
            pb1 = *(const float4*)&Wm  [(size_t)(nB + lr + 64) * HID + k0 + lc];
        }
        #pragma unroll
        for (int ks = 0; ks < 2; ++ks) {
            const int k0s = ks * 8;
            unsigned a[2][4], bf[4][2];
            #pragma unroll
            for (int mi = 0; mi < 2; mi++) {
                int r0 = mBase + mi * 16 + g;
                a[mi][0] = sa[buf][r0    ][k0s + t];
                a[mi][1] = sa[buf][r0 + 8][k0s + t];
                a[mi][2] = sa[buf][r0    ][k0s + t + 4];
                a[mi][3] = sa[buf][r0 + 8][k0s + t + 4];
            }
            #pragma unroll
            for (int ni = 0; ni < 4; ni++) {
                int c0 = nBase + ni * 8 + g;
                bf[ni][0] = sbm[buf][c0][k0s + t];
                bf[ni][1] = sbm[buf][c0][k0s + t + 4];
            }
            #pragma unroll
            for (int mi = 0; mi < 2; mi++)
                #pragma unroll
                for (int ni = 0; ni < 4; ni++) {
                    asm volatile(
                        "mma.sync.aligned.m16n8k8.row.col.f32.tf32.tf32.f32 "
                        "{%0,%1,%2,%3},{%4,%5,%6,%7},{%8,%9},{%0,%1,%2,%3};"
                        : "+f"(acc[mi][ni][0]), "+f"(acc[mi][ni][1]),
                          "+f"(acc[mi][ni][2]), "+f"(acc[mi][ni][3])
                        : "r"(a[mi][0]), "r"(a[mi][1]), "r"(a[mi][2]), "r"(a[mi][3]),
                          "r"(bf[ni][0]), "r"(bf[ni][1]));
                }
        }
        if (kt < NT - 1) {
            int nb = buf ^ 1;
            sa [nb][lr][lc+0] = f2tf32(pa.x);  sa [nb][lr][lc+1] = f2tf32(pa.y);
            sa [nb][lr][lc+2] = f2tf32(pa.z);  sa [nb][lr][lc+3] = f2tf32(pa.w);
            sbm[nb][lr][lc+0] = f2tf32(pb0.x); sbm[nb][lr][lc+1] = f2tf32(pb0.y);
            sbm[nb][lr][lc+2] = f2tf32(pb0.z); sbm[nb][lr][lc+3] = f2tf32(pb0.w);
            sbm[nb][lr+64][lc+0] = f2tf32(pb1.x); sbm[nb][lr+64][lc+1] = f2tf32(pb1.y);
            sbm[nb][lr+64][lc+2] = f2tf32(pb1.z); sbm[nb][lr+64][lc+3] = f2tf32(pb1.w);
        }
        __syncthreads();
    }

    #pragma unroll
    for (int mi = 0; mi < 2; mi++) {
        #pragma unroll
        for (int ni = 0; ni < 4; ni++) {
            int r0 = mB + mBase + mi * 16 + g;
            int c0 = nB + nBase + ni * 8 + t * 2;
            float bm0 = bm[c0], bm1 = bm[c0 + 1];
            out[(size_t)r0 * FOUT + c0]           = acc[mi][ni][0] + bm0;
            out[(size_t)r0 * FOUT + c0 + 1]       = acc[mi][ni][1] + bm1;
            out[(size_t)(r0 + 8) * FOUT + c0]     = acc[mi][ni][2] + bm0;
            out[(size_t)(r0 + 8) * FOUT + c0 + 1] = acc[mi][ni][3] + bm1;
        }
    }
}

// ---------------------------------------------------------------------------
extern "C" void kernel_launch(void* const* d_in, const int* in_sizes, int n_in,
                              void* d_out, int out_size) {
    const float*         x   = (const float*)d_in[0];
    const unsigned char* xm  = (const unsigned char*)d_in[1];
    const float*         W1  = (const float*)d_in[2];
    const float*         b1  = (const float*)d_in[3];
    const float*         W2  = (const float*)d_in[4];
    // d_in[5] = b2: additive constant on pre-softmax logits -> softmax-invariant
    const float*         Wm  = (const float*)d_in[6];
    const float*         bm  = (const float*)d_in[7];
    const float*         G   = (const float*)d_in[8];
    const float*         mub = (const float*)d_in[9];
    float* out = (float*)d_out;

    k_init_att<<<ROWS / 1024, 1024>>>();
    k_cvt_w1<<<512, 256>>>(W1);
    k_mlp_att<<<dim3(4, ROWS / 128), 256>>>(x, b1, W2);
    k_stats_ctx<<<BATCH, 256>>>(x, xm, G, mub);
    k_out2<<<dim3(BATCH / BM2, FOUT / BN2), 256>>>(Wm, bm, out);
}

// round 4
// speedup vs baseline: 1.8503x; 1.0005x over previous
#include <cuda_runtime.h>
#include <cuda_bf16.h>
#include <math.h>
#include <stdint.h>

#define BATCH 512
#define SEQ   196
#define HID   1024
#define MID   512
#define FOUT  2048
#define NB    100
#define ROWS  (BATCH*SEQ)   // 100352

// Scratch (device globals: no allocation allowed)
__device__ __align__(16) float g_att[ROWS];
__device__ __align__(16) float g_ctx[BATCH*HID];
__device__ __align__(16) __nv_bfloat16 g_w1b[MID*HID];   // W1 pre-converted to bf16

// ===========================================================================
// Helpers
// ===========================================================================
__device__ __forceinline__ unsigned pack_bf16(float lo, float hi) {
    unsigned r;
    asm("cvt.rn.bf16x2.f32 %0, %1, %2;" : "=r"(r) : "f"(hi), "f"(lo));
    return r;
}
__device__ __forceinline__ unsigned f2tf32(float x) {
    unsigned y;
    asm("cvt.rna.tf32.f32 %0, %1;" : "=r"(y) : "f"(x));
    return y;
}
__device__ __forceinline__ uint32_t smem_u32(const void* p) {
    uint32_t a;
    asm("{ .reg .u64 t; cvta.to.shared.u64 t, %1; cvt.u32.u64 %0, t; }" : "=r"(a) : "l"(p));
    return a;
}

// 64B-row swizzle (SW64): XOR bits [5:4] with bits [8:7]
#define SWZ64(o) ((o) ^ (((o) >> 3) & 0x30))

#define STS128U(addr, r0, r1, r2, r3) \
    asm volatile("st.shared.v4.b32 [%0], {%1,%2,%3,%4};" \
                 :: "r"(addr), "r"(r0), "r"(r1), "r"(r2), "r"(r3) : "memory")

#define LDSM_X4(r0, r1, r2, r3, addr) \
    asm volatile("ldmatrix.sync.aligned.m8n8.x4.shared.b16 {%0,%1,%2,%3}, [%4];" \
                 : "=r"(r0), "=r"(r1), "=r"(r2), "=r"(r3) : "r"(addr))

#define MMA_BF16(d, a0, a1, a2, a3, b0, b1) \
    asm volatile("mma.sync.aligned.m16n8k16.row.col.f32.bf16.bf16.f32 " \
                 "{%0,%1,%2,%3},{%4,%5,%6,%7},{%8,%9},{%0,%1,%2,%3};" \
                 : "+f"((d)[0]), "+f"((d)[1]), "+f"((d)[2]), "+f"((d)[3]) \
                 : "r"(a0), "r"(a1), "r"(a2), "r"(a3), "r"(b0), "r"(b1))

// ===========================================================================
// Kernel 0: zero att accumulator
// ===========================================================================
__global__ void k_init_att() {
    int i = blockIdx.x * blockDim.x + threadIdx.x;
    if (i < ROWS) g_att[i] = 0.f;
}

// ===========================================================================
// Kernel A: convert W1 (fp32) -> g_w1b (bf16)
// ===========================================================================
__global__ void k_cvt_w1(const float* __restrict__ W1) {
    int i = blockIdx.x * blockDim.x + threadIdx.x;     // 0..131071 (x4 elems)
    float4 v = ((const float4*)W1)[i];
    unsigned u0 = pack_bf16(v.x, v.y);
    unsigned u1 = pack_bf16(v.z, v.w);
    ((uint2*)g_w1b)[i] = make_uint2(u0, u1);
}

// ===========================================================================
// Kernel B: bf16 mma.sync GEMM + fused relu/W2 row-sum epilogue -> g_att
//   BM=128 rows, BN=128 mid-cols, BK=32, double-buffered SW64 smem, ldmatrix.
//   grid (4 n-tiles fastest, 784 row-tiles) for L2 reuse of x.
// ===========================================================================
#define BKG 32          // K per stage (bf16 elems) = 64 bytes/row
#define NKT (HID/BKG)   // 32 iterations

__global__ __launch_bounds__(256, 2)
void k_mlp_att(const float* __restrict__ x,
               const float* __restrict__ b1,
               const float* __restrict__ W2) {
    // 8KB per tile stage; 1024-aligned so SWZ64 (bits 7-8) is base-invariant
    __shared__ __align__(1024) char smA[2][128 * 64];
    __shared__ __align__(1024) char smB[2][128 * 64];
    __shared__ float b1s[128], w2s[128], s_part[128];

    const int tid  = threadIdx.x;
    const int lane = tid & 31;
    const int warp = tid >> 5;
    const int colBase = blockIdx.x * 128;     // n tile (fastest-varying)
    const int rowBase = blockIdx.y * 128;     // row tile

    const uint32_t sa0 = smem_u32(&smA[0][0]);
    const uint32_t sa1 = smem_u32(&smA[1][0]);
    const uint32_t sb0 = smem_u32(&smB[0][0]);
    const uint32_t sb1 = smem_u32(&smB[1][0]);

    if (tid < 128) {
        b1s[tid] = b1[colBase + tid];
        w2s[tid] = W2[colBase + tid];
        s_part[tid] = 0.f;
    }

    // warp tiling: 4 m-warps x 2 n-warps, warp tile 32m x 64n
    const int wm = warp & 3, wn = warp >> 2;
    const int mBase = wm * 32, nBase = wn * 64;
    const int g = lane >> 2, t = lane & 3;

    // ldmatrix lane-address components (offsets within a stage)
    // A: row = mBase + mi*16 + (lane&15), kb = ks*32 + (lane>>4)*16
    const int aRow = mBase + (lane & 15);
    const int aKb  = (lane >> 4) * 16;
    // B: row = nBase + nj*16 + (lane&7) + (lane>>4)*8, kb = ks*32 + ((lane>>3)&1)*16
    const int bRow = nBase + (lane & 7) + ((lane >> 4) * 8);
    const int bKb  = ((lane >> 3) & 1) * 16;

    uint32_t aOff[2][2], bOff[4][2];   // [mi][ks], [nj][ks]  (swizzled, stage-relative)
    #pragma unroll
    for (int mi = 0; mi < 2; mi++)
        #pragma unroll
        for (int ks = 0; ks < 2; ks++)
            aOff[mi][ks] = SWZ64((uint32_t)((aRow + mi * 16) * 64 + ks * 32 + aKb));
    #pragma unroll
    for (int nj = 0; nj < 4; nj++)
        #pragma unroll
        for (int ks = 0; ks < 2; ks++)
            bOff[nj][ks] = SWZ64((uint32_t)((bRow + nj * 16) * 64 + ks * 32 + bKb));

    float acc[2][8][4];
    #pragma unroll
    for (int mi = 0; mi < 2; mi++)
        #pragma unroll
        for (int ni = 0; ni < 8; ni++)
            #pragma unroll
            for (int q = 0; q < 4; q++) acc[mi][ni][q] = 0.f;

    // ---- stage loaders ----
    // A: 128 rows x 32 fp32 -> bf16. 512 tasks of 8 floats, 2 iters.
    const int arow0 = tid >> 2;            // task row for it=0 (task=tid)
    const int ac8   = (tid & 3) * 8;       // float col within k-chunk
    // B: 128 rows x 32 bf16 = 64B rows, 512 tasks of 16B.
    auto ldA = [&](int kc, float4* st) {
        const int k0 = kc * BKG;
        #pragma unroll
        for (int it = 0; it < 2; ++it) {
            int row = arow0 + it * 64;
            const float4* p = (const float4*)(x + (size_t)(rowBase + row) * HID + k0 + ac8);
            st[it * 2]     = p[0];
            st[it * 2 + 1] = p[1];
        }
    };
    auto stA = [&](uint32_t base, const float4* st) {
        #pragma unroll
        for (int it = 0; it < 2; ++it) {
            int row = arow0 + it * 64;
            float4 v0 = st[it * 2], v1 = st[it * 2 + 1];
            unsigned u0 = pack_bf16(v0.x, v0.y), u1 = pack_bf16(v0.z, v0.w);
            unsigned u2 = pack_bf16(v1.x, v1.y), u3 = pack_bf16(v1.z, v1.w);
            uint32_t off = (uint32_t)(row * 64 + ac8 * 2);
            STS128U(base + SWZ64(off), u0, u1, u2, u3);
        }
    };
    auto ldB = [&](int kc, uint4* st) {
        const int k0 = kc * BKG;
        #pragma unroll
        for (int it = 0; it < 2; ++it) {
            int task = tid + it * 256;
            int row = task >> 2;
            int e8  = (task & 3) * 8;   // bf16 element offset
            st[it] = *(const uint4*)(g_w1b + (size_t)(colBase + row) * HID + k0 + e8);
        }
    };
    auto stB = [&](uint32_t base, const uint4* st) {
        #pragma unroll
        for (int it = 0; it < 2; ++it) {
            int task = tid + it * 256;
            int row = task >> 2;
            int c16 = (task & 3) * 16;
            uint32_t off = (uint32_t)(row * 64 + c16);
            STS128U(base + SWZ64(off), st[it].x, st[it].y, st[it].z, st[it].w);
        }
    };

    // prologue: fill stage 0
    {
        float4 fa[4]; uint4 fb[2];
        ldA(0, fa); ldB(0, fb);
        stA(sa0, fa); stB(sb0, fb);
    }
    __syncthreads();

    float4 fa[4]; uint4 fb[2];
    for (int kt = 0; kt < NKT; ++kt) {
        const uint32_t aBase = (kt & 1) ? sa1 : sa0;
        const uint32_t bBase = (kt & 1) ? sb1 : sb0;
        if (kt < NKT - 1) { ldA(kt + 1, fa); ldB(kt + 1, fb); }

        #pragma unroll
        for (int ks = 0; ks < 2; ++ks) {
            uint32_t a[2][4];
            #pragma unroll
            for (int mi = 0; mi < 2; mi++)
                LDSM_X4(a[mi][0], a[mi][1], a[mi][2], a[mi][3], aBase + aOff[mi][ks]);
            #pragma unroll
            for (int nj = 0; nj < 4; nj++) {
                uint32_t b0, b1r, b2, b3;
                LDSM_X4(b0, b1r, b2, b3, bBase + bOff[nj][ks]);
                #pragma unroll
                for (int mi = 0; mi < 2; mi++) {
                    MMA_BF16(acc[mi][nj * 2],     a[mi][0], a[mi][1], a[mi][2], a[mi][3], b0, b1r);
                    MMA_BF16(acc[mi][nj * 2 + 1], a[mi][0], a[mi][1], a[mi][2], a[mi][3], b2, b3);
                }
            }
        }
        if (kt < NKT - 1) {
            const uint32_t aN = (kt & 1) ? sa0 : sa1;
            const uint32_t bN = (kt & 1) ? sb0 : sb1;
            stA(aN, fa); stB(bN, fb);
        }
        __syncthreads();
    }

    // Epilogue: relu(acc + b1) * W2, reduce over this CTA's 128 cols.
    float rs00 = 0.f, rs01 = 0.f, rs10 = 0.f, rs11 = 0.f;
    #pragma unroll
    for (int mi = 0; mi < 2; mi++) {
        float s0 = 0.f, s1 = 0.f;
        #pragma unroll
        for (int ni = 0; ni < 8; ni++) {
            int c = nBase + ni * 8 + t * 2;
            float v0 = fmaxf(acc[mi][ni][0] + b1s[c],     0.f) * w2s[c];
            float v1 = fmaxf(acc[mi][ni][1] + b1s[c + 1], 0.f) * w2s[c + 1];
            float v2 = fmaxf(acc[mi][ni][2] + b1s[c],     0.f) * w2s[c];
            float v3 = fmaxf(acc[mi][ni][3] + b1s[c + 1], 0.f) * w2s[c + 1];
            s0 += v0 + v1;
            s1 += v2 + v3;
        }
        if (mi == 0) { rs00 = s0; rs01 = s1; } else { rs10 = s0; rs11 = s1; }
    }
    #pragma unroll
    for (int off = 1; off < 4; off <<= 1) {
        rs00 += __shfl_xor_sync(0xffffffff, rs00, off);
        rs01 += __shfl_xor_sync(0xffffffff, rs01, off);
        rs10 += __shfl_xor_sync(0xffffffff, rs10, off);
        rs11 += __shfl_xor_sync(0xffffffff, rs11, off);
    }
    if (t == 0) {
        atomicAdd(&s_part[mBase + g],      rs00);
        atomicAdd(&s_part[mBase + 8 + g],  rs01);
        atomicAdd(&s_part[mBase + 16 + g], rs10);
        atomicAdd(&s_part[mBase + 24 + g], rs11);
    }
    __syncthreads();
    if (tid < 128) atomicAdd(&g_att[rowBase + tid], s_part[tid]);
}

// ===========================================================================
// Kernel C: per-batch softmax -> moments -> 2x2 algebra -> r -> w -> context
// ===========================================================================
__global__ __launch_bounds__(256)
void k_stats_ctx(const float* __restrict__ x,
                 const unsigned char* __restrict__ mask,
                 const float* __restrict__ G,
                 const float* __restrict__ mub) {
    __shared__ float sbuf[256];
    __shared__ float r_s[NB];
    __shared__ float w_s[SEQ];

    const int b = blockIdx.x, tid = threadIdx.x;

    float logit = -3.0e38f;
    if (tid < SEQ) {
        logit = g_att[b * SEQ + tid];
        if (mask[b * SEQ + tid]) logit = -1.0e9f;
    }
    sbuf[tid] = logit; __syncthreads();
    for (int s = 128; s > 0; s >>= 1) {
        if (tid < s) sbuf[tid] = fmaxf(sbuf[tid], sbuf[tid + s]);
        __syncthreads();
    }
    float mx = sbuf[0]; __syncthreads();

    float e = (tid < SEQ) ? expf(logit - mx) : 0.f;
    float px = 0.f, py = 0.f;
    if (tid < SEQ) {
        px = (float)(tid / 14) * (1.f / 13.f);
        py = (float)(tid % 14) * (1.f / 13.f);
    }
    float vals[6] = { e, e * px, e * py, e * px * px, e * px * py, e * py * py };
    float sums[6];
    #pragma unroll
    for (int q = 0; q < 6; q++) {
        sbuf[tid] = vals[q]; __syncthreads();
        for (int s = 128; s > 0; s >>= 1) {
            if (tid < s) sbuf[tid] += sbuf[tid + s];
            __syncthreads();
        }
        sums[q] = sbuf[0]; __syncthreads();
    }

    const float S   = sums[0];
    const float Mux = sums[1] / S, Muy = sums[2] / S;
    float S00 = sums[3] / S - Mux * Mux + 1e-6f;
    float S01 = sums[4] / S - Mux * Muy;
    float S11 = sums[5] / S - Muy * Muy + 1e-6f;

    float det = S00 * S11 - S01 * S01;
    float I00 = S11 / det, I01 = -S01 / det, I11 = S00 / det;
    float t0 = I00 * Mux + I01 * Muy;
    float t1 = I01 * Mux + I11 * Muy;
    float ds = I00 * I11 - I01 * I01;
    float R00 = I11 / ds, R01 = -I01 / ds, R11 = I00 / ds;
    float m0 = R00 * t0 + R01 * t1;
    float m1 = R01 * t0 + R11 * t1;
    float A00 = R00 + 1e-3f, A01 = R01, A11 = R11 + 1e-3f;
    float detA = A00 * A11 - A01 * A01;
    float Ai00 = A11 / detA, Ai01 = -A01 / detA, Ai11 = A00 / detA;
    float coef = 1.f / (6.2831853071795864769f * sqrtf(detA));

    if (tid < NB) {
        float d0 = m0 - mub[2 * tid];
        float d1 = m1 - mub[2 * tid + 1];
        float quad = d0 * (Ai00 * d0 + Ai01 * d1) + d1 * (Ai01 * d0 + Ai11 * d1);
        r_s[tid] = expf(-0.5f * quad) * coef;
    }
    __syncthreads();

    if (tid < SEQ) {
        float wv = 0.f;
        #pragma unroll 4
        for (int k = 0; k < NB; k++) wv += G[tid * NB + k] * r_s[k];
        w_s[tid] = wv;
    }
    __syncthreads();

    const float4* xb = (const float4*)(x + (size_t)b * SEQ * HID);
    float ax = 0.f, ay = 0.f, az = 0.f, aw = 0.f;
    #pragma unroll 4
    for (int n = 0; n < SEQ; n++) {
        float4 v = xb[n * (HID / 4) + tid];
        float wv = w_s[n];
        ax += wv * v.x; ay += wv * v.y; az += wv * v.z; aw += wv * v.w;
    }
    float4 o; o.x = ax; o.y = ay; o.z = az; o.w = aw;
    ((float4*)(g_ctx + (size_t)b * HID))[tid] = o;
}

// ===========================================================================
// Kernel D: out = ctx(512x1024) @ Wm^T(1024x2048) + bm   (tf32 mma.sync)
//   BM=64, BN=128, BK=16, 256 threads, grid (8,16) = 128 CTAs
// ===========================================================================
#define BM2 64
#define BN2 128
#define XS2 20

__global__ __launch_bounds__(256, 2)
void k_out2(const float* __restrict__ Wm, const float* __restrict__ bm,
            float* __restrict__ out) {
    __shared__ unsigned sa[2][BM2][XS2];
    __shared__ unsigned sbm[2][BN2][XS2];

    const int tid = threadIdx.x;
    const int mB = blockIdx.x * BM2;
    const int nB = blockIdx.y * BN2;

    const int lr = tid >> 2;          // 0..63
    const int lc = (tid & 3) * 4;     // 0,4,8,12

    const int warp = tid >> 5, lane = tid & 31;
    const int wm = warp & 1, wn = warp >> 1;   // 2 m-warps x 4 n-warps
    const int mBase = wm * 32, nBase = wn * 32;
    const int g = lane >> 2, t = lane & 3;

    float acc[2][4][4];
    #pragma unroll
    for (int mi = 0; mi < 2; mi++)
        #pragma unroll
        for (int ni = 0; ni < 4; ni++)
            #pragma unroll
            for (int q = 0; q < 4; q++) acc[mi][ni][q] = 0.f;

    float4 pa, pb0, pb1;
    {
        pa  = *(const float4*)&g_ctx[(size_t)(mB + lr) * HID + lc];
        pb0 = *(const float4*)&Wm  [(size_t)(nB + lr) * HID + lc];
        pb1 = *(const float4*)&Wm  [(size_t)(nB + lr + 64) * HID + lc];
        sa [0][lr][lc+0] = f2tf32(pa.x);  sa [0][lr][lc+1] = f2tf32(pa.y);
        sa [0][lr][lc+2] = f2tf32(pa.z);  sa [0][lr][lc+3] = f2tf32(pa.w);
        sbm[0][lr][lc+0] = f2tf32(pb0.x); sbm[0][lr][lc+1] = f2tf32(pb0.y);
        sbm[0][lr][lc+2] = f2tf32(pb0.z); sbm[0][lr][lc+3] = f2tf32(pb0.w);
        sbm[0][lr+64][lc+0] = f2tf32(pb1.x); sbm[0][lr+64][lc+1] = f2tf32(pb1.y);
        sbm[0][lr+64][lc+2] = f2tf32(pb1.z); sbm[0][lr+64][lc+3] = f2tf32(pb1.w);
    }
    __syncthreads();

    const int NT = HID / 16;  // 64
    for (int kt = 0; kt < NT; ++kt) {
        const int buf = kt & 1;
        if (kt < NT - 1) {
            int k0 = (kt + 1) * 16;
            pa  = *(const float4*)&g_ctx[(size_t)(mB + lr) * HID + k0 + lc];
            pb0 = *(const float4*)&Wm  [(size_t)(nB + lr) * HID + k0 + lc];
            pb1 = *(const float4*)&Wm  [(size_t)(nB + lr + 64) * HID + k0 + lc];
        }
        #pragma unroll
        for (int ks = 0; ks < 2; ++ks) {
            const int k0s = ks * 8;
            unsigned a[2][4], bf[4][2];
            #pragma unroll
            for (int mi = 0; mi < 2; mi++) {
                int r0 = mBase + mi * 16 + g;
                a[mi][0] = sa[buf][r0    ][k0s + t];
                a[mi][1] = sa[buf][r0 + 8][k0s + t];
                a[mi][2] = sa[buf][r0    ][k0s + t + 4];
                a[mi][3] = sa[buf][r0 + 8][k0s + t + 4];
            }
            #pragma unroll
            for (int ni = 0; ni < 4; ni++) {
                int c0 = nBase + ni * 8 + g;
                bf[ni][0] = sbm[buf][c0][k0s + t];
                bf[ni][1] = sbm[buf][c0][k0s + t + 4];
            }
            #pragma unroll
            for (int mi = 0; mi < 2; mi++)
                #pragma unroll
                for (int ni = 0; ni < 4; ni++) {
                    asm volatile(
                        "mma.sync.aligned.m16n8k8.row.col.f32.tf32.tf32.f32 "
                        "{%0,%1,%2,%3},{%4,%5,%6,%7},{%8,%9},{%0,%1,%2,%3};"
                        : "+f"(acc[mi][ni][0]), "+f"(acc[mi][ni][1]),
                          "+f"(acc[mi][ni][2]), "+f"(acc[mi][ni][3])
                        : "r"(a[mi][0]), "r"(a[mi][1]), "r"(a[mi][2]), "r"(a[mi][3]),
                          "r"(bf[ni][0]), "r"(bf[ni][1]));
                }
        }
        if (kt < NT - 1) {
            int nb = buf ^ 1;
            sa [nb][lr][lc+0] = f2tf32(pa.x);  sa [nb][lr][lc+1] = f2tf32(pa.y);
            sa [nb][lr][lc+2] = f2tf32(pa.z);  sa [nb][lr][lc+3] = f2tf32(pa.w);
            sbm[nb][lr][lc+0] = f2tf32(pb0.x); sbm[nb][lr][lc+1] = f2tf32(pb0.y);
            sbm[nb][lr][lc+2] = f2tf32(pb0.z); sbm[nb][lr][lc+3] = f2tf32(pb0.w);
            sbm[nb][lr+64][lc+0] = f2tf32(pb1.x); sbm[nb][lr+64][lc+1] = f2tf32(pb1.y);
            sbm[nb][lr+64][lc+2] = f2tf32(pb1.z); sbm[nb][lr+64][lc+3] = f2tf32(pb1.w);
        }
        __syncthreads();
    }

    #pragma unroll
    for (int mi = 0; mi < 2; mi++) {
        #pragma unroll
        for (int ni = 0; ni < 4; ni++) {
            int r0 = mB + mBase + mi * 16 + g;
            int c0 = nB + nBase + ni * 8 + t * 2;
            float bm0 = bm[c0], bm1 = bm[c0 + 1];
            out[(size_t)r0 * FOUT + c0]           = acc[mi][ni][0] + bm0;
            out[(size_t)r0 * FOUT + c0 + 1]       = acc[mi][ni][1] + bm1;
            out[(size_t)(r0 + 8) * FOUT + c0]     = acc[mi][ni][2] + bm0;
            out[(size_t)(r0 + 8) * FOUT + c0 + 1] = acc[mi][ni][3] + bm1;
        }
    }
}

// ---------------------------------------------------------------------------
extern "C" void kernel_launch(void* const* d_in, const int* in_sizes, int n_in,
                              void* d_out, int out_size) {
    const float*         x   = (const float*)d_in[0];
    const unsigned char* xm  = (const unsigned char*)d_in[1];
    const float*         W1  = (const float*)d_in[2];
    const float*         b1  = (const float*)d_in[3];
    const float*         W2  = (const float*)d_in[4];
    // d_in[5] = b2: additive constant on pre-softmax logits -> softmax-invariant
    const float*         Wm  = (const float*)d_in[6];
    const float*         bm  = (const float*)d_in[7];
    const float*         G   = (const float*)d_in[8];
    const float*         mub = (const float*)d_in[9];
    float* out = (float*)d_out;

    k_init_att<<<ROWS / 1024, 1024>>>();
    k_cvt_w1<<<512, 256>>>(W1);
    k_mlp_att<<<dim3(4, ROWS / 128), 256>>>(x, b1, W2);
    k_stats_ctx<<<BATCH, 256>>>(x, xm, G, mub);
    k_out2<<<dim3(BATCH / BM2, FOUT / BN2), 256>>>(Wm, bm, out);
}